// round 4
// baseline (speedup 1.0000x reference)
#include <cuda_runtime.h>
#include <math.h>

#define SS 512
#define CC 384
#define HH 12
#define NPROJ 1152   // 192 qs + 192 ks + 192 vs + 144 qp + 144 kp + 288 vp
#define KD 28        // 16 scalar + 4 points * 3
#define VD 40        // 16 scalar + 8 points * 3
#define COMB 576     // 192 scalar_out + 288 pol + 96 norms

// ---------------- scratch (device globals; no allocation allowed) ----------
__device__ float g_Wc[CC * NPROJ];
__device__ float g_bc[NPROJ];
__device__ float g_proj[SS * NPROJ];
__device__ float g_Qc[HH * SS * KD];
__device__ float g_Kc[HH * SS * KD];
__device__ float g_Vc[HH * SS * VD];
__device__ float g_attn[HH * SS * SS];
__device__ float g_out40[HH * SS * VD];
__device__ float g_comb[SS * COMB];
__device__ float g_maskf[SS];

// ---------------- K0: pack weights + biases; block 0 also canonicalizes mask
__global__ void pack_weights(const float* __restrict__ Wq_s, const float* __restrict__ Wk_s,
                             const float* __restrict__ Wv_s, const float* __restrict__ Wq_p,
                             const float* __restrict__ Wk_p, const float* __restrict__ Wv_p,
                             const float* __restrict__ bq_s, const float* __restrict__ bk_s,
                             const float* __restrict__ bv_s, const float* __restrict__ bq_p,
                             const float* __restrict__ bk_p, const float* __restrict__ bv_p,
                             const unsigned char* __restrict__ msk) {
    if (blockIdx.x == 0) {
        __shared__ int flag;
        int t = threadIdx.x;             // 256
        if (t == 0) flag = 0;
        __syncthreads();
        #pragma unroll
        for (int b = t; b < 512; b += 256)
            if ((b & 3) != 0 && msk[b] != 0) atomicOr(&flag, 1);
        __syncthreads();
        for (int i = t; i < SS; i += 256)
            g_maskf[i] = flag ? (msk[i] != 0 ? 1.0f : 0.0f)
                              : (((const int*)msk)[i] != 0 ? 1.0f : 0.0f);
    }
    int total = CC * NPROJ;
    for (int e = blockIdx.x * blockDim.x + threadIdx.x; e < total + NPROJ;
         e += gridDim.x * blockDim.x) {
        if (e < total) {
            int k = e / NPROJ, col = e % NPROJ;
            float v;
            if      (col < 192)  v = Wq_s[k * 192 + col];
            else if (col < 384)  v = Wk_s[k * 192 + (col - 192)];
            else if (col < 576)  v = Wv_s[k * 192 + (col - 384)];
            else if (col < 720)  v = Wq_p[k * 144 + (col - 576)];
            else if (col < 864)  v = Wk_p[k * 144 + (col - 720)];
            else                 v = Wv_p[k * 288 + (col - 864)];
            g_Wc[e] = v;
        } else {
            int col = e - total;
            float v;
            if      (col < 192)  v = bq_s[col];
            else if (col < 384)  v = bk_s[col - 192];
            else if (col < 576)  v = bv_s[col - 384];
            else if (col < 720)  v = bq_p[col - 576];
            else if (col < 864)  v = bk_p[col - 720];
            else                 v = bv_p[col - 864];
            g_bc[col] = v;
        }
    }
}

// ---------------- generic SGEMM: C[M,N] = A[M,K] @ W[K,N] + bias, row mask -
__global__ void gemm64(const float* __restrict__ A, const float* __restrict__ W,
                       const float* __restrict__ bias, float* __restrict__ Cmat,
                       int M, int N, int K, const float* __restrict__ mask) {
    __shared__ __align__(16) float As[16][64];
    __shared__ __align__(16) float Ws[16][64];
    int tid = threadIdx.x;
    int tx = tid & 15, ty = tid >> 4;
    int n0 = blockIdx.x * 64, m0 = blockIdx.y * 64;

    float acc[4][4] = {};
    for (int k0 = 0; k0 < K; k0 += 16) {
        #pragma unroll
        for (int l = 0; l < 4; ++l) {
            int e  = tid + l * 256;
            int kk = e & 15, m = e >> 4;
            As[kk][m] = A[(m0 + m) * K + k0 + kk];
            int n = e & 63, kk2 = e >> 6;
            Ws[kk2][n] = W[(k0 + kk2) * N + n0 + n];
        }
        __syncthreads();
        #pragma unroll
        for (int kk = 0; kk < 16; ++kk) {
            float4 a4 = *(const float4*)&As[kk][ty * 4];
            float4 b4 = *(const float4*)&Ws[kk][tx * 4];
            float av[4] = {a4.x, a4.y, a4.z, a4.w};
            float bv[4] = {b4.x, b4.y, b4.z, b4.w};
            #pragma unroll
            for (int i = 0; i < 4; ++i)
                #pragma unroll
                for (int j = 0; j < 4; ++j) acc[i][j] += av[i] * bv[j];
        }
        __syncthreads();
    }
    #pragma unroll
    for (int i = 0; i < 4; ++i) {
        int m = m0 + ty * 4 + i;
        float sc = mask ? mask[m] : 1.0f;
        #pragma unroll
        for (int j = 0; j < 4; ++j) {
            int n = n0 + tx * 4 + j;
            Cmat[m * N + n] = (acc[i][j] + bias[n]) * sc;
        }
    }
}

// ---------------- K2: rotate points to global frame, pack Q/K/V rows -------
__global__ void rotate_pack(const float* __restrict__ rot, const float* __restrict__ trans) {
    int s = blockIdx.x;
    int t = threadIdx.x;                 // 128 threads
    __shared__ float pts[576];
    __shared__ float Rs[9], ts_[3];
    if (t < 9) Rs[t] = rot[s * 9 + t];
    if (t >= 16 && t < 19) ts_[t - 16] = trans[s * 3 + (t - 16)];
    const float* pr = g_proj + s * NPROJ;

    #pragma unroll
    for (int e = t; e < 576; e += 128) {
        float v = pr[e];
        int seg = e / 192, r = e % 192;
        int h = r >> 4, d = r & 15;
        if      (seg == 0) g_Qc[(h * SS + s) * KD + d] = v;
        else if (seg == 1) g_Kc[(h * SS + s) * KD + d] = v;
        else               g_Vc[(h * SS + s) * VD + d] = v;
    }
    #pragma unroll
    for (int e = t; e < 576; e += 128) pts[e] = pr[576 + e];
    __syncthreads();

    #pragma unroll
    for (int task = t; task < 192; task += 128) {
        const float* p;
        float* o;
        if (task < 48) {
            p = pts + task * 3;
            o = g_Qc + ((task >> 2) * SS + s) * KD + 16 + (task & 3) * 3;
        } else if (task < 96) {
            int q = task - 48;
            p = pts + 144 + q * 3;
            o = g_Kc + ((q >> 2) * SS + s) * KD + 16 + (q & 3) * 3;
        } else {
            int q = task - 96;
            p = pts + 288 + q * 3;
            o = g_Vc + ((q >> 3) * SS + s) * VD + 16 + (q & 7) * 3;
        }
        float x = p[0], y = p[1], z = p[2];
        o[0] = Rs[0] * x + Rs[1] * y + Rs[2] * z + ts_[0];
        o[1] = Rs[3] * x + Rs[4] * y + Rs[5] * z + ts_[1];
        o[2] = Rs[6] * x + Rs[7] * y + Rs[8] * z + ts_[2];
    }
}

// ---------------- K3: logits + softmax. block = (h, 8 queries) -------------
// Low-register variant: K row streamed as float4, only dot[8]/pt[8] live.
__global__ void attn_logits(const float* __restrict__ pw) {
    int h = blockIdx.y;
    int i0 = blockIdx.x * 8;
    __shared__ float qb[8][KD];
    __shared__ float spw[4];
    __shared__ float lg[8][SS];
    int tid = threadIdx.x;

    if (tid < 8 * KD) {
        int il = tid / KD, d = tid % KD;
        qb[il][d] = g_Qc[(h * SS + i0 + il) * KD + d];
    }
    if (tid >= 8 * KD && tid < 8 * KD + 4) {
        float x = pw[h * 4 + (tid - 8 * KD)];
        spw[tid - 8 * KD] = (x > 20.0f) ? x : log1pf(expf(x));
    }
    __syncthreads();

    #pragma unroll
    for (int c = 0; c < 2; ++c) {
        int j = c * 256 + tid;
        const float4* kr = (const float4*)(g_Kc + (h * SS + j) * KD);  // 112B row, 16B aligned
        float dot[8] = {}, pt[8] = {};
        // scalar dims 0..15 : four float4 chunks
        #pragma unroll
        for (int c4 = 0; c4 < 4; ++c4) {
            float4 k4 = kr[c4];
            #pragma unroll
            for (int il = 0; il < 8; ++il) {
                dot[il] += qb[il][c4 * 4 + 0] * k4.x;
                dot[il] += qb[il][c4 * 4 + 1] * k4.y;
                dot[il] += qb[il][c4 * 4 + 2] * k4.z;
                dot[il] += qb[il][c4 * 4 + 3] * k4.w;
            }
        }
        // point dims 16..27 : three float4 chunks covering 4 points x 3
        {
            float4 ka = kr[4], kb = kr[5], kc = kr[6];
            float kp0 = ka.x, kp1 = ka.y, kp2 = ka.z;       // point 0
            float kp3 = ka.w, kp4 = kb.x, kp5 = kb.y;       // point 1
            float kp6 = kb.z, kp7 = kb.w, kp8 = kc.x;       // point 2
            float kp9 = kc.y, kp10 = kc.z, kp11 = kc.w;     // point 3
            float w0 = spw[0], w1 = spw[1], w2 = spw[2], w3 = spw[3];
            #pragma unroll
            for (int il = 0; il < 8; ++il) {
                float dx, dy, dz, d2;
                dx = qb[il][16] - kp0;  dy = qb[il][17] - kp1;  dz = qb[il][18] - kp2;
                d2 = dx * dx + dy * dy + dz * dz;  pt[il] += w0 * d2;
                dx = qb[il][19] - kp3;  dy = qb[il][20] - kp4;  dz = qb[il][21] - kp5;
                d2 = dx * dx + dy * dy + dz * dz;  pt[il] += w1 * d2;
                dx = qb[il][22] - kp6;  dy = qb[il][23] - kp7;  dz = qb[il][24] - kp8;
                d2 = dx * dx + dy * dy + dz * dz;  pt[il] += w2 * d2;
                dx = qb[il][25] - kp9;  dy = qb[il][26] - kp10; dz = qb[il][27] - kp11;
                d2 = dx * dx + dy * dy + dz * dz;  pt[il] += w3 * d2;
            }
        }
        bool vj = g_maskf[j] != 0.0f;
        #pragma unroll
        for (int il = 0; il < 8; ++il)
            lg[il][j] = vj ? (0.25f * dot[il] - 0.5f * pt[il]) : -10000.0f;
    }
    __syncthreads();

    // warp w handles query row w
    int w = tid >> 5, lane = tid & 31;
    float m = -1e30f;
    for (int j = lane; j < SS; j += 32) m = fmaxf(m, lg[w][j]);
    #pragma unroll
    for (int o = 16; o; o >>= 1) m = fmaxf(m, __shfl_xor_sync(0xFFFFFFFFu, m, o));
    float sum = 0.0f;
    for (int j = lane; j < SS; j += 32) {
        float e = __expf(lg[w][j] - m);
        lg[w][j] = e;
        sum += e;
    }
    #pragma unroll
    for (int o = 16; o; o >>= 1) sum += __shfl_xor_sync(0xFFFFFFFFu, sum, o);
    float inv = g_maskf[i0 + w] / sum;
    for (int j = lane; j < SS; j += 32)
        g_attn[(h * SS + i0 + w) * SS + j] = lg[w][j] * inv;
}

// ---------------- K4: out40[h,i,:] = attn[h,i,:] @ Vc[h,:,:] ----------------
// 320 threads: 32 queries x 10 float4 dim-groups.
__global__ void attn_apply() {
    int h = blockIdx.y, i0 = blockIdx.x * 32;
    __shared__ __align__(16) float at[32][64];
    __shared__ __align__(16) float vv[64][VD];
    int tid = threadIdx.x;                // 320
    int il = tid / 10, dg = tid % 10;
    float4 acc = make_float4(0.f, 0.f, 0.f, 0.f);
    for (int j0 = 0; j0 < SS; j0 += 64) {
        for (int e = tid; e < 32 * 64; e += 320)
            at[e >> 6][e & 63] = g_attn[(h * SS + i0 + (e >> 6)) * SS + j0 + (e & 63)];
        for (int e = tid; e < 64 * VD; e += 320)
            vv[e / VD][e % VD] = g_Vc[(h * SS + j0 + e / VD) * VD + (e % VD)];
        __syncthreads();
        #pragma unroll 8
        for (int jj = 0; jj < 64; ++jj) {
            float a = at[il][jj];
            float4 v4 = *(const float4*)&vv[jj][dg * 4];
            acc.x += a * v4.x;  acc.y += a * v4.y;
            acc.z += a * v4.z;  acc.w += a * v4.w;
        }
        __syncthreads();
    }
    *(float4*)&g_out40[(h * SS + i0 + il) * VD + dg * 4] = acc;
}

// ---------------- K5: build combined = [scalar_out | pol | point_norm] -----
__global__ void build_combined(const float* __restrict__ rot, const float* __restrict__ trans) {
    const int NSC = SS * 192;
    const int NPT = SS * 96;
    int idx = blockIdx.x * blockDim.x + threadIdx.x;
    if (idx < NSC) {
        int s = idx / 192, c = idx % 192;
        int h = c >> 4, d = c & 15;
        g_comb[s * COMB + c] = g_out40[(h * SS + s) * VD + d];
    } else if (idx < NSC + NPT) {
        int r = idx - NSC;
        int s = r / 96, q = r % 96;
        int h = q >> 3, p = q & 7;
        const float* o = g_out40 + (h * SS + s) * VD + 16 + 3 * p;
        float v0 = o[0] - trans[s * 3 + 0];
        float v1 = o[1] - trans[s * 3 + 1];
        float v2 = o[2] - trans[s * 3 + 2];
        const float* R = rot + s * 9;
        float p0 = R[0] * v0 + R[3] * v1 + R[6] * v2;
        float p1 = R[1] * v0 + R[4] * v1 + R[7] * v2;
        float p2 = R[2] * v0 + R[5] * v1 + R[8] * v2;
        float* cb = g_comb + s * COMB;
        cb[192 + (h * 8 + p) * 3 + 0] = p0;
        cb[192 + (h * 8 + p) * 3 + 1] = p1;
        cb[192 + (h * 8 + p) * 3 + 2] = p2;
        cb[480 + h * 8 + p] = sqrtf(p0 * p0 + p1 * p1 + p2 * p2);
    }
}

// ---------------------------------------------------------------------------
extern "C" void kernel_launch(void* const* d_in, const int* in_sizes, int n_in,
                              void* d_out, int out_size) {
    const float* single = (const float*)d_in[0];
    const float* rot    = (const float*)d_in[1];
    const float* trans  = (const float*)d_in[2];
    const float* Wq_s = (const float*)d_in[3];  const float* bq_s = (const float*)d_in[4];
    const float* Wk_s = (const float*)d_in[5];  const float* bk_s = (const float*)d_in[6];
    const float* Wv_s = (const float*)d_in[7];  const float* bv_s = (const float*)d_in[8];
    const float* Wq_p = (const float*)d_in[9];  const float* bq_p = (const float*)d_in[10];
    const float* Wk_p = (const float*)d_in[11]; const float* bk_p = (const float*)d_in[12];
    const float* Wv_p = (const float*)d_in[13]; const float* bv_p = (const float*)d_in[14];
    const float* pw   = (const float*)d_in[15];
    const float* Wo   = (const float*)d_in[16];
    const float* bo   = (const float*)d_in[17];
    const unsigned char* mask = (const unsigned char*)d_in[18];
    float* out = (float*)d_out;

    float *pWc, *pbc, *pproj, *pcomb, *pmaskf;
    cudaGetSymbolAddress((void**)&pWc,    g_Wc);
    cudaGetSymbolAddress((void**)&pbc,    g_bc);
    cudaGetSymbolAddress((void**)&pproj,  g_proj);
    cudaGetSymbolAddress((void**)&pcomb,  g_comb);
    cudaGetSymbolAddress((void**)&pmaskf, g_maskf);

    pack_weights<<<512, 256>>>(Wq_s, Wk_s, Wv_s, Wq_p, Wk_p, Wv_p,
                               bq_s, bk_s, bv_s, bq_p, bk_p, bv_p, mask);
    gemm64<<<dim3(NPROJ / 64, SS / 64), 256>>>(single, pWc, pbc, pproj,
                                               SS, NPROJ, CC, (const float*)0);
    rotate_pack<<<SS, 128>>>(rot, trans);
    attn_logits<<<dim3(SS / 8, HH), 256>>>(pw);
    attn_apply<<<dim3(SS / 32, HH), 320>>>();
    build_combined<<<(SS * 192 + SS * 96 + 255) / 256, 256>>>(rot, trans);
    gemm64<<<dim3(CC / 64, SS / 64), 256>>>(pcomb, Wo, bo, out, SS, CC, COMB, pmaskf);
}

// round 5
// speedup vs baseline: 1.2728x; 1.2728x over previous
#include <cuda_runtime.h>
#include <math.h>

#define SS 512
#define CC 384
#define HH 12
#define NPROJ 1152   // 192 qs + 192 ks + 192 vs + 144 qp + 144 kp + 288 vp
#define AD 32        // augmented logit dim (30 used, padded to 32)
#define VD 40        // 16 scalar + 8 points * 3
#define COMB 576     // 192 scalar_out + 288 pol + 96 norms

// ---------------- scratch (device globals; no allocation allowed) ----------
__device__ float g_Wc[CC * NPROJ];
__device__ float g_bc[NPROJ];
__device__ float g_proj[SS * NPROJ];
__device__ float g_Qa[HH * AD * SS];     // dim-major augmented Q
__device__ float g_Ka[HH * AD * SS];     // dim-major augmented K
__device__ float g_Vc[HH * SS * VD];
__device__ float g_attn[HH * SS * SS];
__device__ float g_out40[HH * SS * VD];
__device__ float g_comb[SS * COMB];
__device__ float g_maskf[SS];
__device__ float g_spw[HH * 4];          // softplus(point_weights)

// ---------------- K0: pack weights + biases + mask + softplus weights ------
__global__ void pack_weights(const float* __restrict__ Wq_s, const float* __restrict__ Wk_s,
                             const float* __restrict__ Wv_s, const float* __restrict__ Wq_p,
                             const float* __restrict__ Wk_p, const float* __restrict__ Wv_p,
                             const float* __restrict__ bq_s, const float* __restrict__ bk_s,
                             const float* __restrict__ bv_s, const float* __restrict__ bq_p,
                             const float* __restrict__ bk_p, const float* __restrict__ bv_p,
                             const float* __restrict__ pw,
                             const unsigned char* __restrict__ msk) {
    if (blockIdx.x == 0) {
        __shared__ int flag;
        int t = threadIdx.x;             // 256
        if (t == 0) flag = 0;
        __syncthreads();
        #pragma unroll
        for (int b = t; b < 512; b += 256)
            if ((b & 3) != 0 && msk[b] != 0) atomicOr(&flag, 1);
        __syncthreads();
        for (int i = t; i < SS; i += 256)
            g_maskf[i] = flag ? (msk[i] != 0 ? 1.0f : 0.0f)
                              : (((const int*)msk)[i] != 0 ? 1.0f : 0.0f);
        if (t < HH * 4) {
            float x = pw[t];
            g_spw[t] = (x > 20.0f) ? x : log1pf(expf(x));
        }
    }
    int total = CC * NPROJ;
    for (int e = blockIdx.x * blockDim.x + threadIdx.x; e < total + NPROJ;
         e += gridDim.x * blockDim.x) {
        if (e < total) {
            int k = e / NPROJ, col = e % NPROJ;
            float v;
            if      (col < 192)  v = Wq_s[k * 192 + col];
            else if (col < 384)  v = Wk_s[k * 192 + (col - 192)];
            else if (col < 576)  v = Wv_s[k * 192 + (col - 384)];
            else if (col < 720)  v = Wq_p[k * 144 + (col - 576)];
            else if (col < 864)  v = Wk_p[k * 144 + (col - 720)];
            else                 v = Wv_p[k * 288 + (col - 864)];
            g_Wc[e] = v;
        } else {
            int col = e - total;
            float v;
            if      (col < 192)  v = bq_s[col];
            else if (col < 384)  v = bk_s[col - 192];
            else if (col < 576)  v = bv_s[col - 384];
            else if (col < 720)  v = bq_p[col - 576];
            else if (col < 864)  v = bk_p[col - 720];
            else                 v = bv_p[col - 864];
            g_bc[col] = v;
        }
    }
}

// ---------------- generic SGEMM: C[M,N] = A[M,K] @ W[K,N] + bias, row mask -
__global__ void gemm64(const float* __restrict__ A, const float* __restrict__ W,
                       const float* __restrict__ bias, float* __restrict__ Cmat,
                       int M, int N, int K, const float* __restrict__ mask) {
    __shared__ __align__(16) float As[16][64];
    __shared__ __align__(16) float Ws[16][64];
    int tid = threadIdx.x;
    int tx = tid & 15, ty = tid >> 4;
    int n0 = blockIdx.x * 64, m0 = blockIdx.y * 64;

    float acc[4][4] = {};
    for (int k0 = 0; k0 < K; k0 += 16) {
        #pragma unroll
        for (int l = 0; l < 4; ++l) {
            int e  = tid + l * 256;
            int kk = e & 15, m = e >> 4;
            As[kk][m] = A[(m0 + m) * K + k0 + kk];
            int n = e & 63, kk2 = e >> 6;
            Ws[kk2][n] = W[(k0 + kk2) * N + n0 + n];
        }
        __syncthreads();
        #pragma unroll
        for (int kk = 0; kk < 16; ++kk) {
            float4 a4 = *(const float4*)&As[kk][ty * 4];
            float4 b4 = *(const float4*)&Ws[kk][tx * 4];
            float av[4] = {a4.x, a4.y, a4.z, a4.w};
            float bv[4] = {b4.x, b4.y, b4.z, b4.w};
            #pragma unroll
            for (int i = 0; i < 4; ++i)
                #pragma unroll
                for (int j = 0; j < 4; ++j) acc[i][j] += av[i] * bv[j];
        }
        __syncthreads();
    }
    #pragma unroll
    for (int i = 0; i < 4; ++i) {
        int m = m0 + ty * 4 + i;
        float sc = mask ? mask[m] : 1.0f;
        #pragma unroll
        for (int j = 0; j < 4; ++j) {
            int n = n0 + tx * 4 + j;
            Cmat[m * N + n] = (acc[i][j] + bias[n]) * sc;
        }
    }
}

// ---------------- K2: rotate points, build augmented Q̃/K̃ (dim-major) + V --
__global__ void rotate_pack(const float* __restrict__ rot, const float* __restrict__ trans) {
    int s = blockIdx.x;
    int t = threadIdx.x;                 // 128 threads
    __shared__ float pts[576];
    __shared__ float Rs[9], ts_[3];
    if (t < 9) Rs[t] = rot[s * 9 + t];
    if (t >= 16 && t < 19) ts_[t - 16] = trans[s * 3 + (t - 16)];
    const float* pr = g_proj + s * NPROJ;

    // scalar channels (coalesced read, scattered 4B writes)
    #pragma unroll
    for (int e = t; e < 576; e += 128) {
        float v = pr[e];
        int seg = e / 192, r = e % 192;
        int h = r >> 4, d = r & 15;
        if      (seg == 0) g_Qa[h * (AD * SS) + d * SS + s] = 0.25f * v;
        else if (seg == 1) g_Ka[h * (AD * SS) + d * SS + s] = v;
        else               g_Vc[(h * SS + s) * VD + d] = v;
    }
    #pragma unroll
    for (int e = t; e < 576; e += 128) pts[e] = pr[576 + e];
    __syncthreads();

    if (t < 24) {
        // augmented q/k rows: t<12 -> Q head t ; else K head t-12
        bool isQ = t < 12;
        int h = isQ ? t : t - 12;
        const float* p = pts + (isQ ? 0 : 144) + h * 12;
        float* base = (isQ ? g_Qa : g_Ka) + h * (AD * SS);
        float s2 = 0.0f;
        #pragma unroll
        for (int pp = 0; pp < 4; ++pp) {
            float x = p[pp * 3 + 0], y = p[pp * 3 + 1], z = p[pp * 3 + 2];
            float gx = Rs[0] * x + Rs[1] * y + Rs[2] * z + ts_[0];
            float gy = Rs[3] * x + Rs[4] * y + Rs[5] * z + ts_[1];
            float gz = Rs[6] * x + Rs[7] * y + Rs[8] * z + ts_[2];
            float w = g_spw[h * 4 + pp];
            s2 += w * (gx * gx + gy * gy + gz * gz);
            float m = isQ ? w : 1.0f;
            base[(16 + pp * 3 + 0) * SS + s] = m * gx;
            base[(16 + pp * 3 + 1) * SS + s] = m * gy;
            base[(16 + pp * 3 + 2) * SS + s] = m * gz;
        }
        base[28 * SS + s] = isQ ? -0.5f * s2 : 1.0f;
        base[29 * SS + s] = isQ ? 1.0f : -0.5f * s2;
        base[30 * SS + s] = 0.0f;
        base[31 * SS + s] = 0.0f;
    } else if (t >= 32) {
        int q = t - 32;                   // 96 v-point tasks
        const float* p = pts + 288 + q * 3;
        float* o = g_Vc + ((q >> 3) * SS + s) * VD + 16 + (q & 7) * 3;
        float x = p[0], y = p[1], z = p[2];
        o[0] = Rs[0] * x + Rs[1] * y + Rs[2] * z + ts_[0];
        o[1] = Rs[3] * x + Rs[4] * y + Rs[5] * z + ts_[1];
        o[2] = Rs[6] * x + Rs[7] * y + Rs[8] * z + ts_[2];
    }
}

// ---------------- K3a: logits[h] = Q̃ᵀ K̃  (per-head 512x512x32 GEMM) -------
__global__ void logits_gemm() {
    int h = blockIdx.z;
    int n0 = blockIdx.x * 64, m0 = blockIdx.y * 64;
    __shared__ __align__(16) float Qs[AD][64];
    __shared__ __align__(16) float Ks[AD][64];
    int tid = threadIdx.x;               // 256
    const float* qb = g_Qa + h * (AD * SS);
    const float* kb = g_Ka + h * (AD * SS);
    #pragma unroll
    for (int l = 0; l < 2; ++l) {
        int idx = tid + l * 256;         // 512 float4 slots
        int k = idx >> 4, m4 = idx & 15;
        *(float4*)&Qs[k][m4 * 4] = *(const float4*)&qb[k * SS + m0 + m4 * 4];
        *(float4*)&Ks[k][m4 * 4] = *(const float4*)&kb[k * SS + n0 + m4 * 4];
    }
    __syncthreads();
    int tx = tid & 15, ty = tid >> 4;
    float acc[4][4] = {};
    #pragma unroll
    for (int k = 0; k < AD; ++k) {
        float4 a4 = *(const float4*)&Qs[k][ty * 4];
        float4 b4 = *(const float4*)&Ks[k][tx * 4];
        float av[4] = {a4.x, a4.y, a4.z, a4.w};
        float bv[4] = {b4.x, b4.y, b4.z, b4.w};
        #pragma unroll
        for (int i = 0; i < 4; ++i)
            #pragma unroll
            for (int j = 0; j < 4; ++j) acc[i][j] += av[i] * bv[j];
    }
    #pragma unroll
    for (int i = 0; i < 4; ++i) {
        int m = m0 + ty * 4 + i;
        #pragma unroll
        for (int j = 0; j < 4; ++j) {
            int n = n0 + tx * 4 + j;
            g_attn[(h * SS + m) * SS + n] =
                (g_maskf[n] != 0.0f) ? acc[i][j] : -10000.0f;
        }
    }
}

// ---------------- K3b: softmax over rows of g_attn (warp per row) ----------
__global__ void softmax_rows() {
    int row = blockIdx.x * 8 + (threadIdx.x >> 5);   // 0 .. HH*SS-1
    int lane = threadIdx.x & 31;
    float* r = g_attn + row * SS;
    float4 v[4];
    float m = -1e30f;
    #pragma unroll
    for (int c = 0; c < 4; ++c) {
        v[c] = *(const float4*)&r[(lane + c * 32) * 4];
        m = fmaxf(m, fmaxf(fmaxf(v[c].x, v[c].y), fmaxf(v[c].z, v[c].w)));
    }
    #pragma unroll
    for (int o = 16; o; o >>= 1) m = fmaxf(m, __shfl_xor_sync(0xFFFFFFFFu, m, o));
    float sum = 0.0f;
    #pragma unroll
    for (int c = 0; c < 4; ++c) {
        v[c].x = __expf(v[c].x - m);  v[c].y = __expf(v[c].y - m);
        v[c].z = __expf(v[c].z - m);  v[c].w = __expf(v[c].w - m);
        sum += v[c].x + v[c].y + v[c].z + v[c].w;
    }
    #pragma unroll
    for (int o = 16; o; o >>= 1) sum += __shfl_xor_sync(0xFFFFFFFFu, sum, o);
    float inv = g_maskf[row & (SS - 1)] / sum;
    #pragma unroll
    for (int c = 0; c < 4; ++c) {
        v[c].x *= inv;  v[c].y *= inv;  v[c].z *= inv;  v[c].w *= inv;
        *(float4*)&r[(lane + c * 32) * 4] = v[c];
    }
}

// ---------------- K4: out40[h,i,:] = attn[h,i,:] @ Vc[h,:,:] ----------------
__global__ void attn_apply() {
    int h = blockIdx.y, i0 = blockIdx.x * 32;
    __shared__ float at[32][64];
    __shared__ float vv[64][VD];
    int tid = threadIdx.x;
    int il = tid >> 3, dg = tid & 7;   // 32 queries x 8 dim-groups (5 dims each)
    float acc[5] = {};
    for (int j0 = 0; j0 < SS; j0 += 64) {
        #pragma unroll
        for (int l = 0; l < 8; ++l) {
            int e = tid + l * 256;
            at[e >> 6][e & 63] = g_attn[(h * SS + i0 + (e >> 6)) * SS + j0 + (e & 63)];
        }
        #pragma unroll
        for (int l = 0; l < 10; ++l) {
            int e = tid + l * 256;
            vv[e / VD][e % VD] = g_Vc[(h * SS + j0 + e / VD) * VD + (e % VD)];
        }
        __syncthreads();
        #pragma unroll 8
        for (int jj = 0; jj < 64; ++jj) {
            float a = at[il][jj];
            #pragma unroll
            for (int q = 0; q < 5; ++q) acc[q] += a * vv[jj][dg * 5 + q];
        }
        __syncthreads();
    }
    #pragma unroll
    for (int q = 0; q < 5; ++q)
        g_out40[(h * SS + i0 + il) * VD + dg * 5 + q] = acc[q];
}

// ---------------- K5: build combined = [scalar_out | pol | point_norm] -----
__global__ void build_combined(const float* __restrict__ rot, const float* __restrict__ trans) {
    const int NSC = SS * 192;
    const int NPT = SS * 96;
    int idx = blockIdx.x * blockDim.x + threadIdx.x;
    if (idx < NSC) {
        int s = idx / 192, c = idx % 192;
        int h = c >> 4, d = c & 15;
        g_comb[s * COMB + c] = g_out40[(h * SS + s) * VD + d];
    } else if (idx < NSC + NPT) {
        int r = idx - NSC;
        int s = r / 96, q = r % 96;
        int h = q >> 3, p = q & 7;
        const float* o = g_out40 + (h * SS + s) * VD + 16 + 3 * p;
        float v0 = o[0] - trans[s * 3 + 0];
        float v1 = o[1] - trans[s * 3 + 1];
        float v2 = o[2] - trans[s * 3 + 2];
        const float* R = rot + s * 9;
        float p0 = R[0] * v0 + R[3] * v1 + R[6] * v2;
        float p1 = R[1] * v0 + R[4] * v1 + R[7] * v2;
        float p2 = R[2] * v0 + R[5] * v1 + R[8] * v2;
        float* cb = g_comb + s * COMB;
        cb[192 + (h * 8 + p) * 3 + 0] = p0;
        cb[192 + (h * 8 + p) * 3 + 1] = p1;
        cb[192 + (h * 8 + p) * 3 + 2] = p2;
        cb[480 + h * 8 + p] = sqrtf(p0 * p0 + p1 * p1 + p2 * p2);
    }
}

// ---------------------------------------------------------------------------
extern "C" void kernel_launch(void* const* d_in, const int* in_sizes, int n_in,
                              void* d_out, int out_size) {
    const float* single = (const float*)d_in[0];
    const float* rot    = (const float*)d_in[1];
    const float* trans  = (const float*)d_in[2];
    const float* Wq_s = (const float*)d_in[3];  const float* bq_s = (const float*)d_in[4];
    const float* Wk_s = (const float*)d_in[5];  const float* bk_s = (const float*)d_in[6];
    const float* Wv_s = (const float*)d_in[7];  const float* bv_s = (const float*)d_in[8];
    const float* Wq_p = (const float*)d_in[9];  const float* bq_p = (const float*)d_in[10];
    const float* Wk_p = (const float*)d_in[11]; const float* bk_p = (const float*)d_in[12];
    const float* Wv_p = (const float*)d_in[13]; const float* bv_p = (const float*)d_in[14];
    const float* pw   = (const float*)d_in[15];
    const float* Wo   = (const float*)d_in[16];
    const float* bo   = (const float*)d_in[17];
    const unsigned char* mask = (const unsigned char*)d_in[18];
    float* out = (float*)d_out;

    float *pWc, *pbc, *pproj, *pcomb, *pmaskf;
    cudaGetSymbolAddress((void**)&pWc,    g_Wc);
    cudaGetSymbolAddress((void**)&pbc,    g_bc);
    cudaGetSymbolAddress((void**)&pproj,  g_proj);
    cudaGetSymbolAddress((void**)&pcomb,  g_comb);
    cudaGetSymbolAddress((void**)&pmaskf, g_maskf);

    pack_weights<<<512, 256>>>(Wq_s, Wk_s, Wv_s, Wq_p, Wk_p, Wv_p,
                               bq_s, bk_s, bv_s, bq_p, bk_p, bv_p, pw, mask);
    gemm64<<<dim3(NPROJ / 64, SS / 64), 256>>>(single, pWc, pbc, pproj,
                                               SS, NPROJ, CC, (const float*)0);
    rotate_pack<<<SS, 128>>>(rot, trans);
    logits_gemm<<<dim3(SS / 64, SS / 64, HH), 256>>>();
    softmax_rows<<<HH * SS / 8, 256>>>();
    attn_apply<<<dim3(SS / 32, HH), 256>>>();
    build_combined<<<(SS * 192 + SS * 96 + 255) / 256, 256>>>(rot, trans);
    gemm64<<<dim3(CC / 64, SS / 64), 256>>>(pcomb, Wo, bo, out, SS, CC, COMB, pmaskf);
}

// round 6
// speedup vs baseline: 1.4884x; 1.1694x over previous
#include <cuda_runtime.h>
#include <math.h>

#define SS 512
#define CC 384
#define HH 12
#define NPROJ 1152   // 192 qs + 192 ks + 192 vs + 144 qp + 144 kp + 288 vp
#define AD 32        // augmented logit dim (30 used, padded to 32)
#define VD 40        // 16 scalar + 8 points * 3
#define COMB 576     // 192 scalar_out + 288 pol + 96 norms

// ---------------- scratch (device globals; no allocation allowed) ----------
__device__ float g_Wc[CC * NPROJ];
__device__ float g_bc[NPROJ];
__device__ float g_proj[SS * NPROJ];
__device__ float g_Qa[HH * AD * SS];     // dim-major augmented Q
__device__ float g_Ka[HH * AD * SS];     // dim-major augmented K
__device__ float g_Vc[HH * SS * VD];
__device__ float g_attn[HH * SS * SS];
__device__ float g_out40[HH * SS * VD];
__device__ float g_comb[SS * COMB];
__device__ float g_maskf[SS];
__device__ float g_spw[HH * 4];          // softplus(point_weights)

// ---------------- K0: pack weights (float4 segment copies) + mask + softplus
__global__ void pack_weights(const float* __restrict__ Wq_s, const float* __restrict__ Wk_s,
                             const float* __restrict__ Wv_s, const float* __restrict__ Wq_p,
                             const float* __restrict__ Wk_p, const float* __restrict__ Wv_p,
                             const float* __restrict__ bq_s, const float* __restrict__ bk_s,
                             const float* __restrict__ bv_s, const float* __restrict__ bq_p,
                             const float* __restrict__ bk_p, const float* __restrict__ bv_p,
                             const float* __restrict__ pw,
                             const unsigned char* __restrict__ msk) {
    if (blockIdx.x == 0) {
        __shared__ int flag;
        int t = threadIdx.x;             // 256
        if (t == 0) flag = 0;
        __syncthreads();
        #pragma unroll
        for (int b = t; b < 512; b += 256)
            if ((b & 3) != 0 && msk[b] != 0) atomicOr(&flag, 1);
        __syncthreads();
        for (int i = t; i < SS; i += 256)
            g_maskf[i] = flag ? (msk[i] != 0 ? 1.0f : 0.0f)
                              : (((const int*)msk)[i] != 0 ? 1.0f : 0.0f);
        if (t < HH * 4) {
            float x = pw[t];
            g_spw[t] = (x > 20.0f) ? x : log1pf(expf(x));
        }
    }
    // segment layout per row (float4 units): widths {48,48,48,36,36,72}, total 288
    const int ROW4 = NPROJ / 4;          // 288
    const int TOT4 = CC * ROW4;          // 110592
    float4* dstW = (float4*)g_Wc;
    for (int idx = blockIdx.x * blockDim.x + threadIdx.x; idx < TOT4 + ROW4;
         idx += gridDim.x * blockDim.x) {
        if (idx < TOT4) {
            int row = idx / ROW4, r = idx % ROW4;
            const float* src;  int c4, w4;
            if      (r < 48)  { src = Wq_s; c4 = r;        w4 = 48; }
            else if (r < 96)  { src = Wk_s; c4 = r - 48;   w4 = 48; }
            else if (r < 144) { src = Wv_s; c4 = r - 96;   w4 = 48; }
            else if (r < 180) { src = Wq_p; c4 = r - 144;  w4 = 36; }
            else if (r < 216) { src = Wk_p; c4 = r - 180;  w4 = 36; }
            else              { src = Wv_p; c4 = r - 216;  w4 = 72; }
            dstW[idx] = ((const float4*)src)[row * w4 + c4];
        } else {
            int r = idx - TOT4;
            const float* src;  int c4, dummy;
            if      (r < 48)  { src = bq_s; c4 = r; }
            else if (r < 96)  { src = bk_s; c4 = r - 48; }
            else if (r < 144) { src = bv_s; c4 = r - 96; }
            else if (r < 180) { src = bq_p; c4 = r - 144; }
            else if (r < 216) { src = bk_p; c4 = r - 180; }
            else              { src = bv_p; c4 = r - 216; }
            (void)dummy;
            ((float4*)g_bc)[r] = ((const float4*)src)[c4];
        }
    }
}

// ---------------- generic SGEMM (double-buffered): C = A@W + bias, row mask
__global__ void gemm64(const float* __restrict__ A, const float* __restrict__ W,
                       const float* __restrict__ bias, float* __restrict__ Cmat,
                       int M, int N, int K, const float* __restrict__ mask) {
    __shared__ __align__(16) float As[2][16][64];
    __shared__ __align__(16) float Ws[2][16][64];
    int tid = threadIdx.x;
    int tx = tid & 15, ty = tid >> 4;
    int n0 = blockIdx.x * 64, m0 = blockIdx.y * 64;

    // per-thread load coordinates for the 4 elements of each tile
    int kkA[4], mA[4], nW[4], kkW[4];
    #pragma unroll
    for (int l = 0; l < 4; ++l) {
        int e = tid + l * 256;
        kkA[l] = e & 15;  mA[l] = e >> 4;
        nW[l]  = e & 63;  kkW[l] = e >> 6;
    }
    // prologue: tile 0
    #pragma unroll
    for (int l = 0; l < 4; ++l) {
        As[0][kkA[l]][mA[l]] = A[(m0 + mA[l]) * K + kkA[l]];
        Ws[0][kkW[l]][nW[l]] = W[kkW[l] * N + n0 + nW[l]];
    }
    __syncthreads();

    float acc[4][4] = {};
    int nt = K >> 4;
    for (int t = 0; t < nt; ++t) {
        int cur = t & 1;
        float ar[4], wr[4];
        if (t + 1 < nt) {
            int k0n = (t + 1) << 4;
            #pragma unroll
            for (int l = 0; l < 4; ++l) {
                ar[l] = A[(m0 + mA[l]) * K + k0n + kkA[l]];
                wr[l] = W[(k0n + kkW[l]) * N + n0 + nW[l]];
            }
        }
        #pragma unroll
        for (int kk = 0; kk < 16; ++kk) {
            float4 a4 = *(const float4*)&As[cur][kk][ty * 4];
            float4 b4 = *(const float4*)&Ws[cur][kk][tx * 4];
            float av[4] = {a4.x, a4.y, a4.z, a4.w};
            float bv[4] = {b4.x, b4.y, b4.z, b4.w};
            #pragma unroll
            for (int i = 0; i < 4; ++i)
                #pragma unroll
                for (int j = 0; j < 4; ++j) acc[i][j] += av[i] * bv[j];
        }
        if (t + 1 < nt) {
            #pragma unroll
            for (int l = 0; l < 4; ++l) {
                As[cur ^ 1][kkA[l]][mA[l]] = ar[l];
                Ws[cur ^ 1][kkW[l]][nW[l]] = wr[l];
            }
        }
        __syncthreads();
    }
    #pragma unroll
    for (int i = 0; i < 4; ++i) {
        int m = m0 + ty * 4 + i;
        float sc = mask ? mask[m] : 1.0f;
        #pragma unroll
        for (int j = 0; j < 4; ++j) {
            int n = n0 + tx * 4 + j;
            Cmat[m * N + n] = (acc[i][j] + bias[n]) * sc;
        }
    }
}

// ---------------- K2: rotate points, build augmented Q̃/K̃ (dim-major) + V --
__global__ void rotate_pack(const float* __restrict__ rot, const float* __restrict__ trans) {
    int s = blockIdx.x;
    int t = threadIdx.x;                 // 128 threads
    __shared__ float pts[576];
    __shared__ float Rs[9], ts_[3];
    if (t < 9) Rs[t] = rot[s * 9 + t];
    if (t >= 16 && t < 19) ts_[t - 16] = trans[s * 3 + (t - 16)];
    const float* pr = g_proj + s * NPROJ;

    #pragma unroll
    for (int e = t; e < 576; e += 128) {
        float v = pr[e];
        int seg = e / 192, r = e % 192;
        int h = r >> 4, d = r & 15;
        if      (seg == 0) g_Qa[h * (AD * SS) + d * SS + s] = 0.25f * v;
        else if (seg == 1) g_Ka[h * (AD * SS) + d * SS + s] = v;
        else               g_Vc[(h * SS + s) * VD + d] = v;
    }
    #pragma unroll
    for (int e = t; e < 576; e += 128) pts[e] = pr[576 + e];
    __syncthreads();

    if (t < 24) {
        bool isQ = t < 12;
        int h = isQ ? t : t - 12;
        const float* p = pts + (isQ ? 0 : 144) + h * 12;
        float* base = (isQ ? g_Qa : g_Ka) + h * (AD * SS);
        float s2 = 0.0f;
        #pragma unroll
        for (int pp = 0; pp < 4; ++pp) {
            float x = p[pp * 3 + 0], y = p[pp * 3 + 1], z = p[pp * 3 + 2];
            float gx = Rs[0] * x + Rs[1] * y + Rs[2] * z + ts_[0];
            float gy = Rs[3] * x + Rs[4] * y + Rs[5] * z + ts_[1];
            float gz = Rs[6] * x + Rs[7] * y + Rs[8] * z + ts_[2];
            float w = g_spw[h * 4 + pp];
            s2 += w * (gx * gx + gy * gy + gz * gz);
            float m = isQ ? w : 1.0f;
            base[(16 + pp * 3 + 0) * SS + s] = m * gx;
            base[(16 + pp * 3 + 1) * SS + s] = m * gy;
            base[(16 + pp * 3 + 2) * SS + s] = m * gz;
        }
        base[28 * SS + s] = isQ ? -0.5f * s2 : 1.0f;
        base[29 * SS + s] = isQ ? 1.0f : -0.5f * s2;
        base[30 * SS + s] = 0.0f;
        base[31 * SS + s] = 0.0f;
    } else if (t >= 32) {
        int q = t - 32;                   // 96 v-point tasks
        const float* p = pts + 288 + q * 3;
        float* o = g_Vc + ((q >> 3) * SS + s) * VD + 16 + (q & 7) * 3;
        float x = p[0], y = p[1], z = p[2];
        o[0] = Rs[0] * x + Rs[1] * y + Rs[2] * z + ts_[0];
        o[1] = Rs[3] * x + Rs[4] * y + Rs[5] * z + ts_[1];
        o[2] = Rs[6] * x + Rs[7] * y + Rs[8] * z + ts_[2];
    }
}

// ---------------- K3a: logits[h] = Q̃ᵀ K̃ ; tile 64m x 128n, 8x4 microtile --
__global__ void logits_gemm() {
    int h = blockIdx.z;
    int n0 = blockIdx.x * 128, m0 = blockIdx.y * 64;
    __shared__ __align__(16) float Qs[AD][64];
    __shared__ __align__(16) float Ks[AD][128];
    int tid = threadIdx.x;               // 256
    const float* qb = g_Qa + h * (AD * SS);
    const float* kb = g_Ka + h * (AD * SS);
    #pragma unroll
    for (int l = 0; l < 2; ++l) {
        int idx = tid + l * 256;         // 512 float4 slots for Qs
        int k = idx >> 4, m4 = idx & 15;
        *(float4*)&Qs[k][m4 * 4] = *(const float4*)&qb[k * SS + m0 + m4 * 4];
    }
    #pragma unroll
    for (int l = 0; l < 4; ++l) {
        int idx = tid + l * 256;         // 1024 float4 slots for Ks
        int k = idx >> 5, n4 = idx & 31;
        *(float4*)&Ks[k][n4 * 4] = *(const float4*)&kb[k * SS + n0 + n4 * 4];
    }
    __syncthreads();
    int tx = tid & 31, ty = tid >> 5;    // tx: 32 col-groups, ty: 8 row-groups
    float acc[8][4] = {};
    #pragma unroll
    for (int k = 0; k < AD; ++k) {
        float4 b4 = *(const float4*)&Ks[k][tx * 4];
        float4 a0 = *(const float4*)&Qs[k][ty * 8];
        float4 a1 = *(const float4*)&Qs[k][ty * 8 + 4];
        float av[8] = {a0.x, a0.y, a0.z, a0.w, a1.x, a1.y, a1.z, a1.w};
        float bv[4] = {b4.x, b4.y, b4.z, b4.w};
        #pragma unroll
        for (int i = 0; i < 8; ++i)
            #pragma unroll
            for (int j = 0; j < 4; ++j) acc[i][j] += av[i] * bv[j];
    }
    float4 mq = ((const float4*)g_maskf)[(n0 >> 2) + tx];
    #pragma unroll
    for (int i = 0; i < 8; ++i) {
        int m = m0 + ty * 8 + i;
        float4 v;
        v.x = (mq.x != 0.0f) ? acc[i][0] : -10000.0f;
        v.y = (mq.y != 0.0f) ? acc[i][1] : -10000.0f;
        v.z = (mq.z != 0.0f) ? acc[i][2] : -10000.0f;
        v.w = (mq.w != 0.0f) ? acc[i][3] : -10000.0f;
        *(float4*)&g_attn[(h * SS + m) * SS + n0 + tx * 4] = v;
    }
}

// ---------------- K3b: softmax over rows of g_attn (warp per row) ----------
__global__ void softmax_rows() {
    int row = blockIdx.x * 8 + (threadIdx.x >> 5);   // 0 .. HH*SS-1
    int lane = threadIdx.x & 31;
    float* r = g_attn + row * SS;
    float4 v[4];
    float m = -1e30f;
    #pragma unroll
    for (int c = 0; c < 4; ++c) {
        v[c] = *(const float4*)&r[(lane + c * 32) * 4];
        m = fmaxf(m, fmaxf(fmaxf(v[c].x, v[c].y), fmaxf(v[c].z, v[c].w)));
    }
    #pragma unroll
    for (int o = 16; o; o >>= 1) m = fmaxf(m, __shfl_xor_sync(0xFFFFFFFFu, m, o));
    float sum = 0.0f;
    #pragma unroll
    for (int c = 0; c < 4; ++c) {
        v[c].x = __expf(v[c].x - m);  v[c].y = __expf(v[c].y - m);
        v[c].z = __expf(v[c].z - m);  v[c].w = __expf(v[c].w - m);
        sum += v[c].x + v[c].y + v[c].z + v[c].w;
    }
    #pragma unroll
    for (int o = 16; o; o >>= 1) sum += __shfl_xor_sync(0xFFFFFFFFu, sum, o);
    float inv = g_maskf[row & (SS - 1)] / sum;
    #pragma unroll
    for (int c = 0; c < 4; ++c) {
        v[c].x *= inv;  v[c].y *= inv;  v[c].z *= inv;  v[c].w *= inv;
        *(float4*)&r[(lane + c * 32) * 4] = v[c];
    }
}

// ---------------- K4: out40[h,i,:] = attn[h,i,:] @ Vc[h,:,:] ----------------
__global__ void attn_apply() {
    int h = blockIdx.y, i0 = blockIdx.x * 32;
    __shared__ __align__(16) float at[32][68];   // padded: kills 4-way conflict
    __shared__ __align__(16) float vv[64][VD];
    int tid = threadIdx.x;
    int il = tid >> 3, dg = tid & 7;   // 32 queries x 8 dim-groups (5 dims each)
    float acc[5] = {};
    for (int j0 = 0; j0 < SS; j0 += 64) {
        #pragma unroll
        for (int l = 0; l < 2; ++l) {            // 512 float4 fills of at
            int idx = tid + l * 256;
            int rr = idx >> 4, c4 = idx & 15;
            *(float4*)&at[rr][c4 * 4] =
                *(const float4*)&g_attn[(h * SS + i0 + rr) * SS + j0 + c4 * 4];
        }
        #pragma unroll
        for (int l = 0; l < 3; ++l) {            // 640 float4 fills of vv
            int idx = tid + l * 256;
            if (idx < 640) {
                int rr = idx / 10, c4 = idx % 10;
                *(float4*)&vv[rr][c4 * 4] =
                    ((const float4*)(g_Vc + (h * SS + j0 + rr) * VD))[c4];
            }
        }
        __syncthreads();
        #pragma unroll 8
        for (int jj = 0; jj < 64; ++jj) {
            float a = at[il][jj];
            #pragma unroll
            for (int q = 0; q < 5; ++q) acc[q] += a * vv[jj][dg * 5 + q];
        }
        __syncthreads();
    }
    #pragma unroll
    for (int q = 0; q < 5; ++q)
        g_out40[(h * SS + i0 + il) * VD + dg * 5 + q] = acc[q];
}

// ---------------- K5: build combined = [scalar_out | pol | point_norm] -----
__global__ void build_combined(const float* __restrict__ rot, const float* __restrict__ trans) {
    const int NSC = SS * 192;
    const int NPT = SS * 96;
    int idx = blockIdx.x * blockDim.x + threadIdx.x;
    if (idx < NSC) {
        int s = idx / 192, c = idx % 192;
        int h = c >> 4, d = c & 15;
        g_comb[s * COMB + c] = g_out40[(h * SS + s) * VD + d];
    } else if (idx < NSC + NPT) {
        int r = idx - NSC;
        int s = r / 96, q = r % 96;
        int h = q >> 3, p = q & 7;
        const float* o = g_out40 + (h * SS + s) * VD + 16 + 3 * p;
        float v0 = o[0] - trans[s * 3 + 0];
        float v1 = o[1] - trans[s * 3 + 1];
        float v2 = o[2] - trans[s * 3 + 2];
        const float* R = rot + s * 9;
        float p0 = R[0] * v0 + R[3] * v1 + R[6] * v2;
        float p1 = R[1] * v0 + R[4] * v1 + R[7] * v2;
        float p2 = R[2] * v0 + R[5] * v1 + R[8] * v2;
        float* cb = g_comb + s * COMB;
        cb[192 + (h * 8 + p) * 3 + 0] = p0;
        cb[192 + (h * 8 + p) * 3 + 1] = p1;
        cb[192 + (h * 8 + p) * 3 + 2] = p2;
        cb[480 + h * 8 + p] = sqrtf(p0 * p0 + p1 * p1 + p2 * p2);
    }
}

// ---------------------------------------------------------------------------
extern "C" void kernel_launch(void* const* d_in, const int* in_sizes, int n_in,
                              void* d_out, int out_size) {
    const float* single = (const float*)d_in[0];
    const float* rot    = (const float*)d_in[1];
    const float* trans  = (const float*)d_in[2];
    const float* Wq_s = (const float*)d_in[3];  const float* bq_s = (const float*)d_in[4];
    const float* Wk_s = (const float*)d_in[5];  const float* bk_s = (const float*)d_in[6];
    const float* Wv_s = (const float*)d_in[7];  const float* bv_s = (const float*)d_in[8];
    const float* Wq_p = (const float*)d_in[9];  const float* bq_p = (const float*)d_in[10];
    const float* Wk_p = (const float*)d_in[11]; const float* bk_p = (const float*)d_in[12];
    const float* Wv_p = (const float*)d_in[13]; const float* bv_p = (const float*)d_in[14];
    const float* pw   = (const float*)d_in[15];
    const float* Wo   = (const float*)d_in[16];
    const float* bo   = (const float*)d_in[17];
    const unsigned char* mask = (const unsigned char*)d_in[18];
    float* out = (float*)d_out;

    float *pWc, *pbc, *pproj, *pcomb, *pmaskf;
    cudaGetSymbolAddress((void**)&pWc,    g_Wc);
    cudaGetSymbolAddress((void**)&pbc,    g_bc);
    cudaGetSymbolAddress((void**)&pproj,  g_proj);
    cudaGetSymbolAddress((void**)&pcomb,  g_comb);
    cudaGetSymbolAddress((void**)&pmaskf, g_maskf);

    pack_weights<<<432, 256>>>(Wq_s, Wk_s, Wv_s, Wq_p, Wk_p, Wv_p,
                               bq_s, bk_s, bv_s, bq_p, bk_p, bv_p, pw, mask);
    gemm64<<<dim3(NPROJ / 64, SS / 64), 256>>>(single, pWc, pbc, pproj,
                                               SS, NPROJ, CC, (const float*)0);
    rotate_pack<<<SS, 128>>>(rot, trans);
    logits_gemm<<<dim3(SS / 128, SS / 64, HH), 256>>>();
    softmax_rows<<<HH * SS / 8, 256>>>();
    attn_apply<<<dim3(SS / 32, HH), 256>>>();
    build_combined<<<(SS * 192 + SS * 96 + 255) / 256, 256>>>(rot, trans);
    gemm64<<<dim3(CC / 64, SS / 64), 256>>>(pcomb, Wo, bo, out, SS, CC, COMB, pmaskf);
}